// round 3
// baseline (speedup 1.0000x reference)
#include <cuda_runtime.h>
#include <math.h>

#define NN 100000
#define EE 1600000
#define NW (NN*32)

// ---------------- device scratch (static, no allocation) ----------------
__device__ __align__(16) float g_feats[11][NW];   // h0..h9 (feats[10] never stored)
__device__ __align__(16) float g_preA[NW];        // pre-BN msg GEMM output
__device__ __align__(16) float g_preB[NW];        // pre-BN update GEMM output
__device__ __align__(16) float g_agg[NW];         // gathered messages
__device__ float g_stats[22][64];                 // [slot][0:32]=sum, [32:64]=sumsq
__device__ __align__(16) float g_h256[NN*256];
__device__ __align__(16) float g_h128[NN*128];
__device__ __align__(16) float g_h64[NN*64];
__device__ __align__(16) float g_h32[NW];
// CSR scratch
__device__ int g_deg[NN];
__device__ int g_cursor[NN];
__device__ int g_rowptr[NN+1];
__device__ int g_csrsrc[EE];

__device__ __forceinline__ float lrelu(float x){ return x > 0.f ? x : 0.01f*x; }

// compute fused BN scale/shift for column `lane` from committed stats
__device__ __forceinline__ void bn_coef(int slot, int lane,
                                        const float* __restrict__ g,
                                        const float* __restrict__ be,
                                        float& sc, float& sh){
  float m = g_stats[slot][lane] * (1.f/NN);
  float v = g_stats[slot][32+lane] * (1.f/NN) - m*m;
  float istd = rsqrtf(v + 1e-5f);
  sc = g[lane]*istd;
  sh = fmaf(-m, sc, be[lane]);
}

// ---------------- zero stats + degree ----------------
__global__ void k_zero_stats(){
  int i = blockIdx.x*blockDim.x + threadIdx.x;
  if (i < 22*64) ((float*)g_stats)[i] = 0.f;
  int stride = gridDim.x*blockDim.x;
  for (int j = i; j < NN; j += stride) g_deg[j] = 0;
}

// ---------------- CSR build ----------------
__global__ void k_count(const int* __restrict__ dst){
  int i = blockIdx.x*blockDim.x + threadIdx.x;
  if (i < EE) atomicAdd(&g_deg[dst[i]], 1);
}

__global__ void k_scan(){
  __shared__ int partial[1024];
  const int CH = 98;
  int t = threadIdx.x;
  int beg = t*CH, end = min(beg+CH, NN);
  int s = 0;
  for (int i = beg; i < end; i++) s += g_deg[i];
  partial[t] = s;
  __syncthreads();
  for (int off = 1; off < 1024; off <<= 1){
    int v = partial[t];
    int add = (t >= off) ? partial[t-off] : 0;
    __syncthreads();
    partial[t] = v + add;
    __syncthreads();
  }
  int run = (t > 0) ? partial[t-1] : 0;
  for (int i = beg; i < end; i++){
    g_rowptr[i] = run; g_cursor[i] = run;
    run += g_deg[i];
  }
  if (t == 1023) g_rowptr[NN] = partial[1023];
}

__global__ void k_fill(const int* __restrict__ src, const int* __restrict__ dst){
  int i = blockIdx.x*blockDim.x + threadIdx.x;
  if (i >= EE) return;
  int d = dst[i];
  int p = atomicAdd(&g_cursor[d], 1);
  g_csrsrc[p] = src[i];
}

// ---------------- per-block column-stat commit (256 threads, lane==column) -------
__device__ __forceinline__ void stats_commit(float s, float sq, int slot){
  __shared__ float red[2][8][32];
  int c = threadIdx.x & 31, w = threadIdx.x >> 5;
  red[0][w][c] = s; red[1][w][c] = sq;
  __syncthreads();
  if (w == 0){
    float a = 0.f, b = 0.f;
#pragma unroll
    for (int j = 0; j < 8; j++){ a += red[0][j][c]; b += red[1][j][c]; }
    atomicAdd(&g_stats[slot][c],    a);
    atomicAdd(&g_stats[slot][32+c], b);
  }
}

// ---------------- init layer 0: preA = x * Wi0 + bi0, stats slot 0 ----------------
__global__ void k_init0(const float* __restrict__ x, const float* __restrict__ W0,
                        const float* __restrict__ b0){
  int c = threadIdx.x & 31;
  float wc = W0[c], bc = b0[c];
  float s = 0.f, sq = 0.f;
  int stride = gridDim.x*blockDim.x;
  for (int idx = blockIdx.x*blockDim.x + threadIdx.x; idx < NW; idx += stride){
    float v = fmaf(x[idx >> 5], wc, bc);
    g_preA[idx] = v; s += v; sq += v*v;
  }
  stats_commit(s, sq, 0);
}

// ---------------- fused register-weight small GEMM --------------------------------
// MODE 0: in = feats[fidx] (+ g_agg if K==64)
// MODE 1: in = lrelu(bn(g_preA, preslot))                        [init layer 1]
// MODE 2: in = lrelu(bn(g_preB, preslot)) + feats[ridx]; also STORES in -> feats[fidx]
// out = (outsel? g_preB : g_preA); per-column stats into outslot.
template<int K, int MODE>
__global__ void __launch_bounds__(256) k_gemm3(int fidx, int ridx,
        const float* __restrict__ Wg, const float* __restrict__ bias,
        int preslot, const float* __restrict__ pg, const float* __restrict__ pbe,
        int outsel, int outslot)
{
  __shared__ float in_sh[8][4][K];
  float* out = outsel ? g_preB : g_preA;
  int lane = threadIdx.x & 31, w = threadIdx.x >> 5;
  float wreg[K];
#pragma unroll
  for (int k = 0; k < K; k++) wreg[k] = Wg[k*32 + lane];
  float b = bias[lane];
  float psc = 0.f, psh = 0.f;
  if (MODE >= 1) bn_coef(preslot, lane, pg, pbe, psc, psh);
  const float* in1 = (MODE == 1) ? g_preA : (MODE == 2) ? g_preB : g_feats[fidx];
  const float* resid = (MODE == 2 && ridx >= 0) ? g_feats[ridx] : (const float*)0;
  float* hstore = (MODE == 2) ? g_feats[fidx] : (float*)0;
  float s = 0.f, sq = 0.f;
  int gwarp  = blockIdx.x*8 + w;
  int nwarps = gridDim.x*8;
  for (int grp = gwarp; grp < NN/4; grp += nwarps){
    int r0 = grp*4;
#pragma unroll
    for (int j = 0; j < 4; j++){
      float v = in1[(r0+j)*32 + lane];
      if (MODE >= 1) v = lrelu(fmaf(v, psc, psh));
      if (MODE == 2){
        if (ridx >= 0) v += resid[(r0+j)*32 + lane];
        hstore[(r0+j)*32 + lane] = v;
      }
      in_sh[w][j][lane] = v;
      if (K == 64) in_sh[w][j][32 + lane] = g_agg[(r0+j)*32 + lane];
    }
    __syncwarp();
    float a0=b, a1=b, a2=b, a3=b;
#pragma unroll
    for (int k = 0; k < K; k += 4){
      float4 x0 = *(const float4*)&in_sh[w][0][k];
      float4 x1 = *(const float4*)&in_sh[w][1][k];
      float4 x2 = *(const float4*)&in_sh[w][2][k];
      float4 x3 = *(const float4*)&in_sh[w][3][k];
      a0 = fmaf(x0.x,wreg[k],a0); a0 = fmaf(x0.y,wreg[k+1],a0);
      a0 = fmaf(x0.z,wreg[k+2],a0); a0 = fmaf(x0.w,wreg[k+3],a0);
      a1 = fmaf(x1.x,wreg[k],a1); a1 = fmaf(x1.y,wreg[k+1],a1);
      a1 = fmaf(x1.z,wreg[k+2],a1); a1 = fmaf(x1.w,wreg[k+3],a1);
      a2 = fmaf(x2.x,wreg[k],a2); a2 = fmaf(x2.y,wreg[k+1],a2);
      a2 = fmaf(x2.z,wreg[k+2],a2); a2 = fmaf(x2.w,wreg[k+3],a2);
      a3 = fmaf(x3.x,wreg[k],a3); a3 = fmaf(x3.y,wreg[k+1],a3);
      a3 = fmaf(x3.z,wreg[k+2],a3); a3 = fmaf(x3.w,wreg[k+3],a3);
    }
    __syncwarp();
    out[(r0+0)*32+lane] = a0;
    out[(r0+1)*32+lane] = a1;
    out[(r0+2)*32+lane] = a2;
    out[(r0+3)*32+lane] = a3;
    s  += a0+a1+a2+a3;
    sq += a0*a0+a1*a1+a2*a2+a3*a3;
  }
  stats_commit(s, sq, outslot);
}

// ---------------- CSR pull-gather (ILP-4): agg[d] = sum lrelu(bn(preA[src])) ------
__global__ void __launch_bounds__(256) k_gather(int slot,
        const float* __restrict__ pg, const float* __restrict__ pbe){
  int warp = (blockIdx.x*blockDim.x + threadIdx.x) >> 5;
  int lane = threadIdx.x & 31;
  if (warp >= NN) return;
  float sc, sh;
  bn_coef(slot, lane, pg, pbe, sc, sh);
  int beg = g_rowptr[warp], end = g_rowptr[warp+1];
  float acc = 0.f;
  for (int base = beg; base < end; base += 32){
    int idx = base + lane;
    int s_l = (idx < end) ? g_csrsrc[idx] : 0;
    int nb = min(32, end - base);
    int j = 0;
    for (; j + 4 <= nb; j += 4){
      int s0 = __shfl_sync(0xffffffffu, s_l, j);
      int s1 = __shfl_sync(0xffffffffu, s_l, j+1);
      int s2 = __shfl_sync(0xffffffffu, s_l, j+2);
      int s3 = __shfl_sync(0xffffffffu, s_l, j+3);
      float v0 = g_preA[s0*32 + lane];
      float v1 = g_preA[s1*32 + lane];
      float v2 = g_preA[s2*32 + lane];
      float v3 = g_preA[s3*32 + lane];
      acc += lrelu(fmaf(v0, sc, sh));
      acc += lrelu(fmaf(v1, sc, sh));
      acc += lrelu(fmaf(v2, sc, sh));
      acc += lrelu(fmaf(v3, sc, sh));
    }
    for (; j < nb; j++){
      int ss = __shfl_sync(0xffffffffu, s_l, j);
      float v = g_preA[ss*32 + lane];
      acc += lrelu(fmaf(v, sc, sh));
    }
  }
  g_agg[warp*32 + lane] = acc;
}

// ---------------- final MLP tiled GEMM: out = lrelu(in @ W + b) -------------------
// BN==true (L0 only): in = lrelu(bn(g_preB, preslot)) + feats[ridx]
template<int L> struct MC;
template<> struct MC<0>{ static constexpr int K=32,  C=256, KC=32;  };
template<> struct MC<1>{ static constexpr int K=256, C=128, KC=64;  };
template<> struct MC<2>{ static constexpr int K=128, C=64,  KC=128; };
template<> struct MC<3>{ static constexpr int K=64,  C=32,  KC=64;  };

template<int L, bool BN>
__global__ void __launch_bounds__(256) k_mlp(const float* __restrict__ Wg,
        const float* __restrict__ bias,
        int preslot, const float* __restrict__ pg, const float* __restrict__ pbe, int ridx)
{
  constexpr int K = MC<L>::K, C = MC<L>::C, KC = MC<L>::KC;
  constexpr int PR = 32;
  constexpr int RSUB = 256/C;
  constexpr int RT = PR*RSUB;
  const float* in = BN ? g_preB : (L==1)? g_h256 : (L==2)? g_h128 : g_h64;
  float* out      = (L==0)? g_h256 : (L==1)? g_h128 : (L==2)? g_h64 : g_h32;
  extern __shared__ float smem[];
  float* in_sh = smem;             // RT*K
  float* wT = smem + RT*K;         // C*(KC+4)
  __shared__ float psc[32], psh[32];
  int tid = threadIdx.x;
  if (BN && tid < 32){
    float a, b2; bn_coef(preslot, tid, pg, pbe, a, b2);
    psc[tid] = a; psh[tid] = b2;
  }
  if (BN) __syncthreads();
  int c = tid % C, rg = tid / C;
  int row0 = blockIdx.x * RT;
  const float* resid = (BN && ridx >= 0) ? g_feats[ridx] : (const float*)0;
  for (int i = tid; i < RT*K; i += 256){
    int r = i / K, k = i % K;
    int row = row0 + r;
    float v = 0.f;
    if (row < NN){
      v = in[row*K + k];
      if (BN){
        v = lrelu(fmaf(v, psc[k], psh[k]));
        if (ridx >= 0) v += resid[row*K + k];
      }
    }
    in_sh[i] = v;
  }
  float acc[PR];
  float b = bias[c];
#pragma unroll
  for (int j = 0; j < PR; j++) acc[j] = b;
  for (int k0 = 0; k0 < K; k0 += KC){
    __syncthreads();
    for (int i = tid; i < KC*C; i += 256){
      int k = i / C, cc = i % C;
      wT[cc*(KC+4)+k] = Wg[(k0+k)*C + cc];
    }
    __syncthreads();
#pragma unroll 4
    for (int k = 0; k < KC; k += 4){
      float4 wv = *(const float4*)&wT[c*(KC+4)+k];
#pragma unroll
      for (int j = 0; j < PR; j++){
        int r = rg*PR + j;
        float4 a = *(const float4*)&in_sh[r*K + k0 + k];
        acc[j] += a.x*wv.x + a.y*wv.y + a.z*wv.z + a.w*wv.w;
      }
    }
  }
#pragma unroll
  for (int j = 0; j < PR; j++){
    int row = row0 + rg*PR + j;
    if (row < NN) out[row*C + c] = lrelu(acc[j]);
  }
}

// ---------------- sigmoid head ----------------
__global__ void k_head(const float* __restrict__ Wo, const float* __restrict__ bo,
                       float* __restrict__ out){
  __shared__ float w[32];
  if (threadIdx.x < 32) w[threadIdx.x] = Wo[threadIdx.x];
  __syncthreads();
  int n = blockIdx.x*blockDim.x + threadIdx.x;
  if (n >= NN) return;
  const float4* hp = (const float4*)(g_h32 + n*32);
  const float4* wp = (const float4*)w;
  float z = bo[0];
#pragma unroll
  for (int q = 0; q < 8; q++){
    float4 a = hp[q]; float4 ww = wp[q];
    z += a.x*ww.x + a.y*ww.y + a.z*ww.z + a.w*ww.w;
  }
  out[n] = 1.f/(1.f + expf(-z));
}

// ---------------- launch ----------------
extern "C" void kernel_launch(void* const* d_in, const int* in_sizes, int n_in,
                              void* d_out, int out_size){
  const float* x    = (const float*)d_in[0];
  const int*   col  = (const int*)d_in[1];
  const float* Wi0  = (const float*)d_in[2];
  const float* bi0  = (const float*)d_in[3];
  const float* gi0  = (const float*)d_in[4];
  const float* bei0 = (const float*)d_in[5];
  const float* Wi1  = (const float*)d_in[6];
  const float* bi1  = (const float*)d_in[7];
  const float* gi1  = (const float*)d_in[8];
  const float* bei1 = (const float*)d_in[9];
  const float* Wm   = (const float*)d_in[10];
  const float* bm   = (const float*)d_in[11];
  const float* gm   = (const float*)d_in[12];
  const float* bem  = (const float*)d_in[13];
  const float* Wu   = (const float*)d_in[14];
  const float* bu   = (const float*)d_in[15];
  const float* gu   = (const float*)d_in[16];
  const float* beu  = (const float*)d_in[17];
  const float* Wf0  = (const float*)d_in[18];
  const float* bf0  = (const float*)d_in[19];
  const float* Wf1  = (const float*)d_in[20];
  const float* bf1  = (const float*)d_in[21];
  const float* Wf2  = (const float*)d_in[22];
  const float* bf2  = (const float*)d_in[23];
  const float* Wf3  = (const float*)d_in[24];
  const float* bf3  = (const float*)d_in[25];
  const float* Wo   = (const float*)d_in[26];
  const float* bo   = (const float*)d_in[27];
  const int* src = col;
  const int* dst = col + EE;

  cudaFuncSetAttribute(k_mlp<1,false>, cudaFuncAttributeMaxDynamicSharedMemorySize, 100352);
  cudaFuncSetAttribute(k_mlp<2,false>, cudaFuncAttributeMaxDynamicSharedMemorySize, 99328);
  cudaFuncSetAttribute(k_mlp<3,false>, cudaFuncAttributeMaxDynamicSharedMemorySize, 74240);

  // CSR build
  k_zero_stats<<<440,256>>>();
  k_count<<<(EE+255)/256,256>>>(dst);
  k_scan<<<1,1024>>>();
  k_fill<<<(EE+255)/256,256>>>(src, dst);

  // init MLP
  k_init0<<<1184,256>>>(x, Wi0, bi0);
  // layer i1: in = bnlrelu(preA, slot0) -> preB, stats slot1
  k_gemm3<32,1><<<296,256>>>(-1, -1, Wi1, bi1, 0, gi0, bei0, /*out=B*/1, 1);

  for (int i = 0; i < 10; i++){
    int sm = 2 + 2*i, su = 3 + 2*i;
    int prevslot = (i == 0) ? 1 : 3 + 2*(i-1);
    const float* pg  = (i == 0) ? gi1  : gu  + (i-1)*32;
    const float* pbe = (i == 0) ? bei1 : beu + (i-1)*32;
    // msg GEMM: h_i = bnlrelu(preB, prevslot) + feats[i-3]; store feats[i]; out preA
    k_gemm3<32,2><<<296,256>>>(i, (i >= 3) ? i-3 : -1, Wm + i*1024, bm + i*32,
                               prevslot, pg, pbe, /*out=A*/0, sm);
    k_gather<<<(NN*32+255)/256,256>>>(sm, gm + i*32, bem + i*32);
    // update GEMM: concat(feats[i], agg) -> preB, stats su
    k_gemm3<64,0><<<296,256>>>(i, -1, Wu + i*2048, bu + i*32,
                               0, (const float*)0, (const float*)0, /*out=B*/1, su);
  }

  // final MLP; L0 fuses h10 = bnlrelu(preB, slot21) + feats[7]
  k_mlp<0,true> <<<(NN+31)/32,   256, 40960 >>>(Wf0, bf0, 21, gu + 9*32, beu + 9*32, 7);
  k_mlp<1,false><<<(NN+63)/64,   256, 100352>>>(Wf1, bf1, 0, (const float*)0, (const float*)0, -1);
  k_mlp<2,false><<<(NN+127)/128, 256, 99328 >>>(Wf2, bf2, 0, (const float*)0, (const float*)0, -1);
  k_mlp<3,false><<<(NN+255)/256, 256, 74240 >>>(Wf3, bf3, 0, (const float*)0, (const float*)0, -1);
  k_head<<<(NN+255)/256,256>>>(Wo, bo, (float*)d_out);
}

// round 5
// speedup vs baseline: 1.1047x; 1.1047x over previous
#include <cuda_runtime.h>
#include <math.h>
#include <stdint.h>

#define NN 100000
#define EE 1600000
#define NW (NN*32)

// ---------------- device scratch (static, no allocation) ----------------
__device__ __align__(16) float g_feats[11][NW];   // h after init + each layer
__device__ __align__(16) float g_preA[NW];        // pre-BN buffer A (msg pre)
__device__ __align__(16) float g_preB[NW];        // pre-BN buffer B (update pre)
__device__ __align__(16) float g_agg[NW];         // gathered messages
__device__ float g_stats[22][64];                 // [slot][0:32]=sum, [32:64]=sumsq
__device__ __align__(16) float g_scale[22][32];
__device__ __align__(16) float g_shift[22][32];
__device__ __align__(16) float g_h256[NN*256];    // row-major [NN][256]
__device__ __align__(16) float g_h128[NN*128];
__device__ __align__(16) float g_h64[NN*64];
__device__ __align__(16) float g_h32[NW];
// CSR scratch
__device__ int g_deg[NN];
__device__ int g_cursor[NN];
__device__ int g_rowptr[NN+1];
__device__ int g_csrsrc[EE];

__device__ __forceinline__ float lrelu(float x){ return x > 0.f ? x : 0.01f*x; }

// ---------------- tf32 helpers (base ISA, sm_80+) ----------------
__device__ __forceinline__ uint32_t f2tf32(float x){
  uint32_t r; asm("cvt.rna.tf32.f32 %0, %1;" : "=r"(r) : "f"(x)); return r;
}
__device__ __forceinline__ void tf32_split(float x, uint32_t& hi, uint32_t& lo){
  uint32_t h = f2tf32(x);
  hi = h;
  lo = f2tf32(x - __uint_as_float(h));
}
__device__ __forceinline__ void mma_tf32(float* c, const uint32_t* a, const uint32_t* b){
  asm volatile("mma.sync.aligned.m16n8k8.row.col.f32.tf32.tf32.f32 "
    "{%0,%1,%2,%3}, {%4,%5,%6,%7}, {%8,%9}, {%0,%1,%2,%3};"
    : "+f"(c[0]), "+f"(c[1]), "+f"(c[2]), "+f"(c[3])
    : "r"(a[0]), "r"(a[1]), "r"(a[2]), "r"(a[3]), "r"(b[0]), "r"(b[1]));
}

// ---------------- zero kernels ----------------
__global__ void k_zero_stats(){
  int i = blockIdx.x*blockDim.x + threadIdx.x;
  if (i < 22*64) ((float*)g_stats)[i] = 0.f;
  int stride = gridDim.x*blockDim.x;
  for (int j = i; j < NN; j += stride) g_deg[j] = 0;
}

// ---------------- CSR build ----------------
__global__ void k_count(const int* __restrict__ dst){
  int i = blockIdx.x*blockDim.x + threadIdx.x;
  if (i < EE) atomicAdd(&g_deg[dst[i]], 1);
}

__global__ void k_scan(){
  __shared__ int partial[1024];
  const int CH = 98;
  int t = threadIdx.x;
  int beg = t*CH, end = min(beg+CH, NN);
  int s = 0;
  for (int i = beg; i < end; i++) s += g_deg[i];
  partial[t] = s;
  __syncthreads();
  for (int off = 1; off < 1024; off <<= 1){
    int v = partial[t];
    int add = (t >= off) ? partial[t-off] : 0;
    __syncthreads();
    partial[t] = v + add;
    __syncthreads();
  }
  int run = (t > 0) ? partial[t-1] : 0;
  for (int i = beg; i < end; i++){
    g_rowptr[i] = run; g_cursor[i] = run;
    run += g_deg[i];
  }
  if (t == 1023) g_rowptr[NN] = partial[1023];
}

__global__ void k_fill(const int* __restrict__ src, const int* __restrict__ dst){
  int i = blockIdx.x*blockDim.x + threadIdx.x;
  if (i >= EE) return;
  int d = dst[i];
  int p = atomicAdd(&g_cursor[d], 1);
  g_csrsrc[p] = src[i];
}

// ---------------- per-block column-stat commit ----------------
__device__ __forceinline__ void stats_commit(float s, float sq, int slot){
  __shared__ float red[2][8][32];
  int c = threadIdx.x & 31, w = threadIdx.x >> 5;
  red[0][w][c] = s; red[1][w][c] = sq;
  __syncthreads();
  if (w == 0){
    float a = 0.f, b = 0.f;
#pragma unroll
    for (int j = 0; j < 8; j++){ a += red[0][j][c]; b += red[1][j][c]; }
    atomicAdd(&g_stats[slot][c],    a);
    atomicAdd(&g_stats[slot][32+c], b);
  }
}

// ---------------- init layer 0 ----------------
__global__ void k_init0(const float* __restrict__ x, const float* __restrict__ W0,
                        const float* __restrict__ b0){
  int c = threadIdx.x & 31;
  float wc = W0[c], bc = b0[c];
  float s = 0.f, sq = 0.f;
  int stride = gridDim.x*blockDim.x;
  for (int idx = blockIdx.x*blockDim.x + threadIdx.x; idx < NW; idx += stride){
    float v = fmaf(x[idx >> 5], wc, bc);
    g_preA[idx] = v; s += v; sq += v*v;
  }
  stats_commit(s, sq, 0);
}

// ---------------- finalize BN stats into fused scale/shift ----------------
__global__ void k_finalize(int slot, const float* __restrict__ g,
                           const float* __restrict__ be){
  int c = threadIdx.x;
  float m = g_stats[slot][c] * (1.f/NN);
  float v = g_stats[slot][32+c] * (1.f/NN) - m*m;
  float istd = rsqrtf(v + 1e-5f);
  float sc = g[c]*istd;
  g_scale[slot][c] = sc;
  g_shift[slot][c] = fmaf(-m, sc, be[c]);
}

// ---------------- register-weight small GEMM --------------------------------------
template<int K, bool PRE>
__global__ void __launch_bounds__(256) k_gemm2(int fidx, const float* __restrict__ Wg,
        const float* __restrict__ bias, int outsel, int preslot, int outslot)
{
  __shared__ float in_sh[8][4][K];
  const float* in1 = PRE ? g_preA : g_feats[fidx];
  float* out = outsel ? g_preB : g_preA;
  int lane = threadIdx.x & 31, w = threadIdx.x >> 5;
  float wreg[K];
#pragma unroll
  for (int k = 0; k < K; k++) wreg[k] = Wg[k*32 + lane];
  float b = bias[lane];
  float psc = 0.f, psh = 0.f;
  if (PRE){ psc = g_scale[preslot][lane]; psh = g_shift[preslot][lane]; }
  float s = 0.f, sq = 0.f;
  int gwarp  = blockIdx.x*8 + w;
  int nwarps = gridDim.x*8;
  for (int grp = gwarp; grp < NN/4; grp += nwarps){
    int r0 = grp*4;
#pragma unroll
    for (int j = 0; j < 4; j++){
      float v = in1[(r0+j)*32 + lane];
      if (PRE) v = lrelu(fmaf(v, psc, psh));
      in_sh[w][j][lane] = v;
      if (K == 64) in_sh[w][j][32 + lane] = g_agg[(r0+j)*32 + lane];
    }
    __syncwarp();
    float a0=b, a1=b, a2=b, a3=b;
#pragma unroll
    for (int k = 0; k < K; k += 4){
      float4 x0 = *(const float4*)&in_sh[w][0][k];
      float4 x1 = *(const float4*)&in_sh[w][1][k];
      float4 x2 = *(const float4*)&in_sh[w][2][k];
      float4 x3 = *(const float4*)&in_sh[w][3][k];
      a0 = fmaf(x0.x,wreg[k],a0); a0 = fmaf(x0.y,wreg[k+1],a0);
      a0 = fmaf(x0.z,wreg[k+2],a0); a0 = fmaf(x0.w,wreg[k+3],a0);
      a1 = fmaf(x1.x,wreg[k],a1); a1 = fmaf(x1.y,wreg[k+1],a1);
      a1 = fmaf(x1.z,wreg[k+2],a1); a1 = fmaf(x1.w,wreg[k+3],a1);
      a2 = fmaf(x2.x,wreg[k],a2); a2 = fmaf(x2.y,wreg[k+1],a2);
      a2 = fmaf(x2.z,wreg[k+2],a2); a2 = fmaf(x2.w,wreg[k+3],a2);
      a3 = fmaf(x3.x,wreg[k],a3); a3 = fmaf(x3.y,wreg[k+1],a3);
      a3 = fmaf(x3.z,wreg[k+2],a3); a3 = fmaf(x3.w,wreg[k+3],a3);
    }
    __syncwarp();
    out[(r0+0)*32+lane] = a0;
    out[(r0+1)*32+lane] = a1;
    out[(r0+2)*32+lane] = a2;
    out[(r0+3)*32+lane] = a3;
    s  += a0+a1+a2+a3;
    sq += a0*a0+a1*a1+a2*a2+a3*a3;
  }
  stats_commit(s, sq, outslot);
}

// ---------------- CSR pull-gather (ILP-8) ----------------
__global__ void __launch_bounds__(256) k_gather(int slot){
  int warp = (blockIdx.x*blockDim.x + threadIdx.x) >> 5;
  int lane = threadIdx.x & 31;
  if (warp >= NN) return;
  float sc = g_scale[slot][lane], sh = g_shift[slot][lane];
  int beg = g_rowptr[warp], end = g_rowptr[warp+1];
  float acc = 0.f;
  for (int base = beg; base < end; base += 32){
    int idx = base + lane;
    int s_l = (idx < end) ? g_csrsrc[idx] : 0;
    int nb = min(32, end - base);
    int j = 0;
    for (; j + 8 <= nb; j += 8){
      int s0 = __shfl_sync(0xffffffffu, s_l, j);
      int s1 = __shfl_sync(0xffffffffu, s_l, j+1);
      int s2 = __shfl_sync(0xffffffffu, s_l, j+2);
      int s3 = __shfl_sync(0xffffffffu, s_l, j+3);
      int s4 = __shfl_sync(0xffffffffu, s_l, j+4);
      int s5 = __shfl_sync(0xffffffffu, s_l, j+5);
      int s6 = __shfl_sync(0xffffffffu, s_l, j+6);
      int s7 = __shfl_sync(0xffffffffu, s_l, j+7);
      float v0 = g_preA[s0*32 + lane];
      float v1 = g_preA[s1*32 + lane];
      float v2 = g_preA[s2*32 + lane];
      float v3 = g_preA[s3*32 + lane];
      float v4 = g_preA[s4*32 + lane];
      float v5 = g_preA[s5*32 + lane];
      float v6 = g_preA[s6*32 + lane];
      float v7 = g_preA[s7*32 + lane];
      acc += lrelu(fmaf(v0, sc, sh));
      acc += lrelu(fmaf(v1, sc, sh));
      acc += lrelu(fmaf(v2, sc, sh));
      acc += lrelu(fmaf(v3, sc, sh));
      acc += lrelu(fmaf(v4, sc, sh));
      acc += lrelu(fmaf(v5, sc, sh));
      acc += lrelu(fmaf(v6, sc, sh));
      acc += lrelu(fmaf(v7, sc, sh));
    }
    for (; j < nb; j++){
      int ss = __shfl_sync(0xffffffffu, s_l, j);
      float v = g_preA[ss*32 + lane];
      acc += lrelu(fmaf(v, sc, sh));
    }
  }
  g_agg[warp*32 + lane] = acc;
}

// ---------------- apply BN+lrelu (+residual) ----------------
__global__ void k_actstore(int slot, int ridx, int oidx){
  int c = threadIdx.x & 31;
  float sc = g_scale[slot][c], sh = g_shift[slot][c];
  const float* resid = (ridx >= 0) ? g_feats[ridx] : (const float*)0;
  float* dstp = g_feats[oidx];
  int stride = gridDim.x*blockDim.x;
  for (int i = blockIdx.x*blockDim.x + threadIdx.x; i < NW; i += stride){
    float v = lrelu(fmaf(g_preB[i], sc, sh));
    if (ridx >= 0) v += resid[i];
    dstp[i] = v;
  }
}

// ---------------- final MLP via mma.sync tf32 (3xTF32 precision) -----------------
// out[m][c] = lrelu( sum_k in[m][k]*W[k][c] + b[c] )
// block = 256 thr (8 warps); warp tile = 16 rows x NSUB*8 cols; block = 128 rows.
template<int L> struct FC;
template<> struct FC<0>{ static constexpr int K=32,  C=256; };
template<> struct FC<1>{ static constexpr int K=256, C=128; };
template<> struct FC<2>{ static constexpr int K=128, C=64;  };
template<> struct FC<3>{ static constexpr int K=64,  C=32;  };

template<int L>
__global__ void __launch_bounds__(256) k_fmma(const float* __restrict__ Wg,
                                              const float* __restrict__ bias){
  constexpr int K = FC<L>::K, C = FC<L>::C;
  constexpr int NSUB = (C >= 64) ? 8 : C/8;
  const float* in = (L==0)? g_feats[10] : (L==1)? g_h256 : (L==2)? g_h128 : g_h64;
  float* out      = (L==0)? g_h256 : (L==1)? g_h128 : (L==2)? g_h64 : g_h32;
  int lane = threadIdx.x & 31, w = threadIdx.x >> 5;
  int rowW = blockIdx.x*128 + w*16;
  int colW = blockIdx.y*(NSUB*8);
  int g = lane >> 2, tig = lane & 3;
  int r0 = rowW + g, r1 = r0 + 8;

  float acc[NSUB][4];
#pragma unroll
  for (int s = 0; s < NSUB; s++){
    acc[s][0] = 0.f; acc[s][1] = 0.f; acc[s][2] = 0.f; acc[s][3] = 0.f;
  }

  const float* inA0 = in + (size_t)r0*K;
  const float* inA1 = in + (size_t)r1*K;
  bool v0 = (r0 < NN), v1 = (r1 < NN);

#pragma unroll 2
  for (int k0 = 0; k0 < K; k0 += 8){
    int ka = k0 + tig;
    float x0 = v0 ? inA0[ka]     : 0.f;
    float x1 = v1 ? inA1[ka]     : 0.f;
    float x2 = v0 ? inA0[ka + 4] : 0.f;
    float x3 = v1 ? inA1[ka + 4] : 0.f;
    uint32_t aH[4], aL[4];
    tf32_split(x0, aH[0], aL[0]);
    tf32_split(x1, aH[1], aL[1]);
    tf32_split(x2, aH[2], aL[2]);
    tf32_split(x3, aH[3], aL[3]);

    uint32_t bH[NSUB][2], bL[NSUB][2];
#pragma unroll
    for (int s = 0; s < NSUB; s++){
      int col = colW + s*8 + g;
      float w0 = Wg[(size_t)ka*C + col];
      float w1 = Wg[(size_t)(ka+4)*C + col];
      tf32_split(w0, bH[s][0], bL[s][0]);
      tf32_split(w1, bH[s][1], bL[s][1]);
    }
#pragma unroll
    for (int s = 0; s < NSUB; s++){
      mma_tf32(acc[s], aH, bH[s]);
      mma_tf32(acc[s], aH, bL[s]);
      mma_tf32(acc[s], aL, bH[s]);
    }
  }

#pragma unroll
  for (int s = 0; s < NSUB; s++){
    int c0 = colW + s*8 + 2*tig;
    float b0 = bias[c0], b1 = bias[c0+1];
    if (v0){
      out[(size_t)r0*C + c0]     = lrelu(acc[s][0] + b0);
      out[(size_t)r0*C + c0 + 1] = lrelu(acc[s][1] + b1);
    }
    if (v1){
      out[(size_t)r1*C + c0]     = lrelu(acc[s][2] + b0);
      out[(size_t)r1*C + c0 + 1] = lrelu(acc[s][3] + b1);
    }
  }
}

// ---------------- sigmoid head ----------------
__global__ void k_head(const float* __restrict__ Wo, const float* __restrict__ bo,
                       float* __restrict__ out){
  __shared__ float w[32];
  if (threadIdx.x < 32) w[threadIdx.x] = Wo[threadIdx.x];
  __syncthreads();
  int n = blockIdx.x*blockDim.x + threadIdx.x;
  if (n >= NN) return;
  const float4* hp = (const float4*)(g_h32 + n*32);
  const float4* wp = (const float4*)w;
  float z = bo[0];
#pragma unroll
  for (int q = 0; q < 8; q++){
    float4 a = hp[q]; float4 ww = wp[q];
    z += a.x*ww.x + a.y*ww.y + a.z*ww.z + a.w*ww.w;
  }
  out[n] = 1.f/(1.f + expf(-z));
}

// ---------------- launch ----------------
extern "C" void kernel_launch(void* const* d_in, const int* in_sizes, int n_in,
                              void* d_out, int out_size){
  const float* x    = (const float*)d_in[0];
  const int*   col  = (const int*)d_in[1];
  const float* Wi0  = (const float*)d_in[2];
  const float* bi0  = (const float*)d_in[3];
  const float* gi0  = (const float*)d_in[4];
  const float* bei0 = (const float*)d_in[5];
  const float* Wi1  = (const float*)d_in[6];
  const float* bi1  = (const float*)d_in[7];
  const float* gi1  = (const float*)d_in[8];
  const float* bei1 = (const float*)d_in[9];
  const float* Wm   = (const float*)d_in[10];
  const float* bm   = (const float*)d_in[11];
  const float* gm   = (const float*)d_in[12];
  const float* bem  = (const float*)d_in[13];
  const float* Wu   = (const float*)d_in[14];
  const float* bu   = (const float*)d_in[15];
  const float* gu   = (const float*)d_in[16];
  const float* beu  = (const float*)d_in[17];
  const float* Wf0  = (const float*)d_in[18];
  const float* bf0  = (const float*)d_in[19];
  const float* Wf1  = (const float*)d_in[20];
  const float* bf1  = (const float*)d_in[21];
  const float* Wf2  = (const float*)d_in[22];
  const float* bf2  = (const float*)d_in[23];
  const float* Wf3  = (const float*)d_in[24];
  const float* bf3  = (const float*)d_in[25];
  const float* Wo   = (const float*)d_in[26];
  const float* bo   = (const float*)d_in[27];
  const int* src = col;
  const int* dst = col + EE;

  // CSR build
  k_zero_stats<<<440,256>>>();
  k_count<<<(EE+255)/256,256>>>(dst);
  k_scan<<<1,1024>>>();
  k_fill<<<(EE+255)/256,256>>>(src, dst);

  // init MLP
  k_init0<<<1184,256>>>(x, Wi0, bi0);
  k_finalize<<<1,32>>>(0, gi0, bei0);
  k_gemm2<32,true><<<296,256>>>(0, Wi1, bi1, /*out=B*/1, /*preslot*/0, /*outslot*/1);
  k_finalize<<<1,32>>>(1, gi1, bei1);
  k_actstore<<<1184,256>>>(1, -1, 0);                    // feats[0]

  for (int i = 0; i < 10; i++){
    int sm = 2 + 2*i, su = 3 + 2*i;
    k_gemm2<32,false><<<296,256>>>(i, Wm + i*1024, bm + i*32, /*out=A*/0, -1, sm);
    k_finalize<<<1,32>>>(sm, gm + i*32, bem + i*32);
    k_gather<<<(NN*32+255)/256,256>>>(sm);
    k_gemm2<64,false><<<296,256>>>(i, Wu + i*2048, bu + i*32, /*out=B*/1, -1, su);
    k_finalize<<<1,32>>>(su, gu + i*32, beu + i*32);
    k_actstore<<<1184,256>>>(su, (i >= 2) ? (i-2) : -1, i+1);
  }

  // final MLP on mma.sync tf32 (3xTF32)
  const int MB = (NN + 127)/128;  // 782
  dim3 g0(MB, 4); k_fmma<0><<<g0,256>>>(Wf0, bf0);
  dim3 g1(MB, 2); k_fmma<1><<<g1,256>>>(Wf1, bf1);
  dim3 g2(MB, 1); k_fmma<2><<<g2,256>>>(Wf2, bf2);
  dim3 g3(MB, 1); k_fmma<3><<<g3,256>>>(Wf3, bf3);
  k_head<<<(NN+255)/256,256>>>(Wo, bo, (float*)d_out);
}